// round 1
// baseline (speedup 1.0000x reference)
#include <cuda_runtime.h>
#include <cuda_bf16.h>

// SubgraphProjection: out[s,:] = sum over edges e with row_idx[e]==s of
//                     values[e] * X[col_idx[e], :]
// row_idx is sorted (CSR-like), DIM=128, NUM_SEGMENTS = out_size/128.
//
// Strategy: one warp per segment. Binary-search the sorted row_idx for the
// segment's [start,end) edge range, then accumulate float4 per lane
// (lane L owns dims [4L, 4L+4)). Edge (col,val) pairs are staged 32-at-a-time
// per warp and broadcast with __shfl_sync. No atomics; every segment writes
// its output row (zeros for empty segments), so the poisoned d_out is fully
// initialized.

#define DIMV 32   // 128 floats = 32 float4 per row

__global__ __launch_bounds__(256) void SubgraphProjection_kernel(
    const float4* __restrict__ X,      // [num_nodes, 32] as float4
    const float*  __restrict__ vals,   // [nnz]
    const int*    __restrict__ rows,   // [nnz], sorted
    const int*    __restrict__ cols,   // [nnz]
    float4*       __restrict__ out,    // [num_segments, 32] as float4
    int nnz, int num_segments)
{
    const int warp = (blockIdx.x * blockDim.x + threadIdx.x) >> 5;
    const int lane = threadIdx.x & 31;
    if (warp >= num_segments) return;

    // lower_bound(rows, warp) — all lanes redundantly (broadcast loads, cheap)
    int lo = 0, hi = nnz;
    while (lo < hi) {
        int mid = (lo + hi) >> 1;
        if (__ldg(&rows[mid]) < warp) lo = mid + 1; else hi = mid;
    }
    const int start = lo;

    // lower_bound(rows, warp+1) starting from start
    hi = nnz;
    while (lo < hi) {
        int mid = (lo + hi) >> 1;
        if (__ldg(&rows[mid]) < warp + 1) lo = mid + 1; else hi = mid;
    }
    const int end = lo;

    float4 acc = make_float4(0.f, 0.f, 0.f, 0.f);

    for (int e0 = start; e0 < end; e0 += 32) {
        const int n = min(32, end - e0);
        int   c = 0;
        float v = 0.f;
        if (lane < n) {
            c = __ldg(&cols[e0 + lane]);
            v = __ldg(&vals[e0 + lane]);
        }
        #pragma unroll 4
        for (int j = 0; j < n; ++j) {
            const int   cj = __shfl_sync(0xffffffffu, c, j);
            const float vj = __shfl_sync(0xffffffffu, v, j);
            const float4 x = __ldg(&X[(long)cj * DIMV + lane]);
            acc.x += vj * x.x;
            acc.y += vj * x.y;
            acc.z += vj * x.z;
            acc.w += vj * x.w;
        }
    }

    out[(long)warp * DIMV + lane] = acc;
}

extern "C" void kernel_launch(void* const* d_in, const int* in_sizes, int n_in,
                              void* d_out, int out_size)
{
    const float4* X    = (const float4*)d_in[0];  // input_matrix [num_nodes*128] f32
    const float*  vals = (const float*) d_in[1];  // values [nnz]
    const int*    rows = (const int*)   d_in[2];  // row_idx [nnz], sorted
    const int*    cols = (const int*)   d_in[3];  // col_idx [nnz]
    float4*       out  = (float4*)      d_out;

    const int nnz          = in_sizes[1];
    const int num_segments = out_size / 128;

    const int threads = 256;                       // 8 warps per block
    const int warps_needed = num_segments;
    const int blocks = (warps_needed * 32 + threads - 1) / threads;

    SubgraphProjection_kernel<<<blocks, threads>>>(X, vals, rows, cols, out,
                                                   nnz, num_segments);
}

// round 2
// speedup vs baseline: 1.3702x; 1.3702x over previous
#include <cuda_runtime.h>
#include <cuda_bf16.h>

// SubgraphProjection: out[s,:] = sum_{e: rows[e]==s} vals[e] * X[cols[e],:]
// rows sorted (CSR-like), DIM=128.
//
// Pass 1 (build_offsets): turn sorted rows[] into CSR row pointers in a
//   __device__ scratch array (boundary detection, handles empty segments).
// Pass 2 (gather): one warp per segment; lane L owns dims [4L,4L+4) (float4).
//   Edge indices/values read via broadcast __ldg (uniform address -> one L1
//   wavefront; the 128B line serves 32 consecutive edges). 8-wide unrolled
//   gather with 4 accumulator chains for deep MLP. No atomics; every segment
//   writes its row (zeros if empty) so the poisoned d_out is fully set.

#define DIMV 32              // 128 floats = 32 float4
#define MAX_SEG (1 << 20)    // scratch capacity (num_segments = 50000)

__device__ int g_seg[MAX_SEG + 1];

__global__ void build_offsets_kernel(const int* __restrict__ rows,
                                     int nnz, int num_segments)
{
    const int e = blockIdx.x * blockDim.x + threadIdx.x;
    if (e >= nnz) return;
    const int r  = rows[e];
    const int rp = (e == 0) ? -1 : rows[e - 1];
    // fill boundaries (covers empty segments between rp and r)
    for (int s = rp + 1; s <= r; ++s) g_seg[s] = e;
    if (e == nnz - 1) {
        for (int s = r + 1; s <= num_segments; ++s) g_seg[s] = nnz;
    }
}

__global__ __launch_bounds__(256) void gather_kernel(
    const float4* __restrict__ X,     // [num_nodes, 32] float4
    const float*  __restrict__ vals,  // [nnz]
    const int*    __restrict__ cols,  // [nnz]
    float4*       __restrict__ out,   // [num_segments, 32] float4
    int num_segments)
{
    const int warp = (blockIdx.x * blockDim.x + threadIdx.x) >> 5;
    const int lane = threadIdx.x & 31;
    if (warp >= num_segments) return;

    const int start = g_seg[warp];
    const int end   = g_seg[warp + 1];

    float4 a0 = make_float4(0.f,0.f,0.f,0.f);
    float4 a1 = make_float4(0.f,0.f,0.f,0.f);
    float4 a2 = make_float4(0.f,0.f,0.f,0.f);
    float4 a3 = make_float4(0.f,0.f,0.f,0.f);

    int e = start;
    #pragma unroll 1
    for (; e + 8 <= end; e += 8) {
        // uniform-address broadcast loads (one L1 wavefront each, line-reused)
        const int c0 = __ldg(cols + e + 0), c1 = __ldg(cols + e + 1);
        const int c2 = __ldg(cols + e + 2), c3 = __ldg(cols + e + 3);
        const int c4 = __ldg(cols + e + 4), c5 = __ldg(cols + e + 5);
        const int c6 = __ldg(cols + e + 6), c7 = __ldg(cols + e + 7);
        const float v0 = __ldg(vals + e + 0), v1 = __ldg(vals + e + 1);
        const float v2 = __ldg(vals + e + 2), v3 = __ldg(vals + e + 3);
        const float v4 = __ldg(vals + e + 4), v5 = __ldg(vals + e + 5);
        const float v6 = __ldg(vals + e + 6), v7 = __ldg(vals + e + 7);

        // 8 independent 512B row reads in flight
        const float4 x0 = __ldg(&X[c0 * DIMV + lane]);
        const float4 x1 = __ldg(&X[c1 * DIMV + lane]);
        const float4 x2 = __ldg(&X[c2 * DIMV + lane]);
        const float4 x3 = __ldg(&X[c3 * DIMV + lane]);
        const float4 x4 = __ldg(&X[c4 * DIMV + lane]);
        const float4 x5 = __ldg(&X[c5 * DIMV + lane]);
        const float4 x6 = __ldg(&X[c6 * DIMV + lane]);
        const float4 x7 = __ldg(&X[c7 * DIMV + lane]);

        a0.x += v0*x0.x; a0.y += v0*x0.y; a0.z += v0*x0.z; a0.w += v0*x0.w;
        a1.x += v1*x1.x; a1.y += v1*x1.y; a1.z += v1*x1.z; a1.w += v1*x1.w;
        a2.x += v2*x2.x; a2.y += v2*x2.y; a2.z += v2*x2.z; a2.w += v2*x2.w;
        a3.x += v3*x3.x; a3.y += v3*x3.y; a3.z += v3*x3.z; a3.w += v3*x3.w;
        a0.x += v4*x4.x; a0.y += v4*x4.y; a0.z += v4*x4.z; a0.w += v4*x4.w;
        a1.x += v5*x5.x; a1.y += v5*x5.y; a1.z += v5*x5.z; a1.w += v5*x5.w;
        a2.x += v6*x6.x; a2.y += v6*x6.y; a2.z += v6*x6.z; a2.w += v6*x6.w;
        a3.x += v7*x7.x; a3.y += v7*x7.y; a3.z += v7*x7.z; a3.w += v7*x7.w;
    }
    // remainder
    for (; e < end; ++e) {
        const int   c = __ldg(cols + e);
        const float v = __ldg(vals + e);
        const float4 x = __ldg(&X[c * DIMV + lane]);
        a0.x += v*x.x; a0.y += v*x.y; a0.z += v*x.z; a0.w += v*x.w;
    }

    float4 r;
    r.x = (a0.x + a1.x) + (a2.x + a3.x);
    r.y = (a0.y + a1.y) + (a2.y + a3.y);
    r.z = (a0.z + a1.z) + (a2.z + a3.z);
    r.w = (a0.w + a1.w) + (a2.w + a3.w);
    out[warp * DIMV + lane] = r;
}

extern "C" void kernel_launch(void* const* d_in, const int* in_sizes, int n_in,
                              void* d_out, int out_size)
{
    const float4* X    = (const float4*)d_in[0];  // input_matrix, f32 [nodes*128]
    const float*  vals = (const float*) d_in[1];  // values [nnz]
    const int*    rows = (const int*)   d_in[2];  // row_idx [nnz], sorted
    const int*    cols = (const int*)   d_in[3];  // col_idx [nnz]
    float4*       out  = (float4*)      d_out;

    const int nnz          = in_sizes[1];
    int num_segments       = out_size / 128;
    if (num_segments > MAX_SEG) num_segments = MAX_SEG;  // safety clamp

    build_offsets_kernel<<<(nnz + 255) / 256, 256>>>(rows, nnz, num_segments);

    const int threads = 256;  // 8 warps/block
    const int blocks  = (num_segments * 32 + threads - 1) / threads;
    gather_kernel<<<blocks, threads>>>(X, vals, cols, out, num_segments);
}

// round 4
// speedup vs baseline: 1.3714x; 1.0009x over previous
#include <cuda_runtime.h>
#include <cuda_fp16.h>

// SubgraphProjection: out[s,:] = sum_{e: rows[e]==s} vals[e] * X[cols[e],:]
// rows sorted, DIM=128. L2-bandwidth bound => halve gather traffic by
// pre-converting X to fp16 scratch (rel_err ~1e-4 << 1e-3 gate, fp32 accum).
//
// Kernel 1 (prep, fused): blocks [0, CB) convert X fp32 -> fp16 scratch
//   (8 floats/thread -> one 16B store); blocks [CB, ...) build CSR row
//   pointers from sorted rows[] by boundary detection.
// Kernel 2 (gather): one warp per segment, lane L owns dims [4L,4L+4):
//   one 8B (half4) load per row per lane -> 256B/row through L2 instead of
//   512B. 8-wide unrolled, 4 fp32 accumulator chains. No atomics.

#define DIMV   32            // 128 floats = 32 float4 (output)
#define MAX_SEG (1 << 20)
#define NODES_CAP 131072     // capacity in rows (dataset: 100000)

__device__ int   g_seg[MAX_SEG + 1];
__device__ uint4 g_xh[NODES_CAP * 16];   // fp16 X: 16 x 16B groups per row

// bit-cast helpers (the named intrinsics don't exist in cuda_fp16.h)
__device__ __forceinline__ unsigned h2_as_u32(__half2 h) {
    union { __half2 h; unsigned u; } c; c.h = h; return c.u;
}
__device__ __forceinline__ __half2 u32_as_h2(unsigned u) {
    union { unsigned u; __half2 h; } c; c.u = u; return c.h;
}

__global__ __launch_bounds__(256) void prep_kernel(
    const float4* __restrict__ X,      // [nodes*32] float4
    const int*    __restrict__ rows,   // [nnz] sorted
    int nnz, int num_segments,
    int n_groups,                      // nodes*16 (8 floats per group)
    int convert_blocks)
{
    if ((int)blockIdx.x < convert_blocks) {
        // ---- convert X fp32 -> fp16 ----
        const int g = blockIdx.x * 256 + threadIdx.x;
        if (g >= n_groups) return;
        const float4 f0 = __ldg(&X[g * 2 + 0]);
        const float4 f1 = __ldg(&X[g * 2 + 1]);
        uint4 h;
        h.x = h2_as_u32(__floats2half2_rn(f0.x, f0.y));
        h.y = h2_as_u32(__floats2half2_rn(f0.z, f0.w));
        h.z = h2_as_u32(__floats2half2_rn(f1.x, f1.y));
        h.w = h2_as_u32(__floats2half2_rn(f1.z, f1.w));
        g_xh[g] = h;
    } else {
        // ---- build CSR offsets from sorted rows ----
        const int e = (blockIdx.x - convert_blocks) * 256 + threadIdx.x;
        if (e >= nnz) return;
        const int r  = __ldg(&rows[e]);
        const int rp = (e == 0) ? -1 : __ldg(&rows[e - 1]);
        for (int s = rp + 1; s <= r; ++s) g_seg[s] = e;
        if (e == nnz - 1)
            for (int s = r + 1; s <= num_segments; ++s) g_seg[s] = nnz;
    }
}

__global__ __launch_bounds__(256) void gather_kernel(
    const float* __restrict__ vals,   // [nnz]
    const int*   __restrict__ cols,   // [nnz]
    float4*      __restrict__ out,    // [num_segments, 32] float4
    int num_segments)
{
    const int warp = (blockIdx.x * blockDim.x + threadIdx.x) >> 5;
    const int lane = threadIdx.x & 31;
    if (warp >= num_segments) return;

    const int start = g_seg[warp];
    const int end   = g_seg[warp + 1];

    // fp16 X viewed as uint2 (half4): 32 x 8B per row; lane L -> dims [4L,4L+4)
    const uint2* __restrict__ Xh = reinterpret_cast<const uint2*>(g_xh);

    float4 a0 = make_float4(0.f,0.f,0.f,0.f);
    float4 a1 = make_float4(0.f,0.f,0.f,0.f);
    float4 a2 = make_float4(0.f,0.f,0.f,0.f);
    float4 a3 = make_float4(0.f,0.f,0.f,0.f);

    int e = start;
    #pragma unroll 1
    for (; e + 8 <= end; e += 8) {
        const int c0 = __ldg(cols+e+0), c1 = __ldg(cols+e+1);
        const int c2 = __ldg(cols+e+2), c3 = __ldg(cols+e+3);
        const int c4 = __ldg(cols+e+4), c5 = __ldg(cols+e+5);
        const int c6 = __ldg(cols+e+6), c7 = __ldg(cols+e+7);
        const float v0 = __ldg(vals+e+0), v1 = __ldg(vals+e+1);
        const float v2 = __ldg(vals+e+2), v3 = __ldg(vals+e+3);
        const float v4 = __ldg(vals+e+4), v5 = __ldg(vals+e+5);
        const float v6 = __ldg(vals+e+6), v7 = __ldg(vals+e+7);

        // 8 independent 256B row reads in flight
        const uint2 h0 = Xh[c0 * 32 + lane];
        const uint2 h1 = Xh[c1 * 32 + lane];
        const uint2 h2 = Xh[c2 * 32 + lane];
        const uint2 h3 = Xh[c3 * 32 + lane];
        const uint2 h4 = Xh[c4 * 32 + lane];
        const uint2 h5 = Xh[c5 * 32 + lane];
        const uint2 h6 = Xh[c6 * 32 + lane];
        const uint2 h7 = Xh[c7 * 32 + lane];

        float2 p, q;
        p = __half22float2(u32_as_h2(h0.x)); q = __half22float2(u32_as_h2(h0.y));
        a0.x += v0*p.x; a0.y += v0*p.y; a0.z += v0*q.x; a0.w += v0*q.y;
        p = __half22float2(u32_as_h2(h1.x)); q = __half22float2(u32_as_h2(h1.y));
        a1.x += v1*p.x; a1.y += v1*p.y; a1.z += v1*q.x; a1.w += v1*q.y;
        p = __half22float2(u32_as_h2(h2.x)); q = __half22float2(u32_as_h2(h2.y));
        a2.x += v2*p.x; a2.y += v2*p.y; a2.z += v2*q.x; a2.w += v2*q.y;
        p = __half22float2(u32_as_h2(h3.x)); q = __half22float2(u32_as_h2(h3.y));
        a3.x += v3*p.x; a3.y += v3*p.y; a3.z += v3*q.x; a3.w += v3*q.y;
        p = __half22float2(u32_as_h2(h4.x)); q = __half22float2(u32_as_h2(h4.y));
        a0.x += v4*p.x; a0.y += v4*p.y; a0.z += v4*q.x; a0.w += v4*q.y;
        p = __half22float2(u32_as_h2(h5.x)); q = __half22float2(u32_as_h2(h5.y));
        a1.x += v5*p.x; a1.y += v5*p.y; a1.z += v5*q.x; a1.w += v5*q.y;
        p = __half22float2(u32_as_h2(h6.x)); q = __half22float2(u32_as_h2(h6.y));
        a2.x += v6*p.x; a2.y += v6*p.y; a2.z += v6*q.x; a2.w += v6*q.y;
        p = __half22float2(u32_as_h2(h7.x)); q = __half22float2(u32_as_h2(h7.y));
        a3.x += v7*p.x; a3.y += v7*p.y; a3.z += v7*q.x; a3.w += v7*q.y;
    }
    for (; e < end; ++e) {
        const int   c = __ldg(cols + e);
        const float v = __ldg(vals + e);
        const uint2 h = Xh[c * 32 + lane];
        const float2 p = __half22float2(u32_as_h2(h.x));
        const float2 q = __half22float2(u32_as_h2(h.y));
        a0.x += v*p.x; a0.y += v*p.y; a0.z += v*q.x; a0.w += v*q.y;
    }

    float4 r;
    r.x = (a0.x + a1.x) + (a2.x + a3.x);
    r.y = (a0.y + a1.y) + (a2.y + a3.y);
    r.z = (a0.z + a1.z) + (a2.z + a3.z);
    r.w = (a0.w + a1.w) + (a2.w + a3.w);
    out[warp * DIMV + lane] = r;
}

extern "C" void kernel_launch(void* const* d_in, const int* in_sizes, int n_in,
                              void* d_out, int out_size)
{
    const float4* X    = (const float4*)d_in[0];
    const float*  vals = (const float*) d_in[1];
    const int*    rows = (const int*)   d_in[2];
    const int*    cols = (const int*)   d_in[3];
    float4*       out  = (float4*)      d_out;

    const int nnz   = in_sizes[1];
    int nodes       = in_sizes[0] / 128;
    if (nodes > NODES_CAP) nodes = NODES_CAP;
    int num_segments = out_size / 128;
    if (num_segments > MAX_SEG) num_segments = MAX_SEG;

    const int n_groups       = nodes * 16;                    // 8 floats/group
    const int convert_blocks = (n_groups + 255) / 256;
    const int offset_blocks  = (nnz + 255) / 256;

    prep_kernel<<<convert_blocks + offset_blocks, 256>>>(
        X, rows, nnz, num_segments, n_groups, convert_blocks);

    const int threads = 256;
    const int blocks  = (num_segments * 32 + threads - 1) / threads;
    gather_kernel<<<blocks, threads>>>(vals, cols, out, num_segments);
}

// round 6
// speedup vs baseline: 1.5992x; 1.1661x over previous
#include <cuda_runtime.h>
#include <cuda_fp16.h>

// SubgraphProjection: out[s,:] = sum_{e: rows[e]==s} vals[e] * X[cols[e],:]
// rows sorted, DIM=128. fp16 scratch for X (halved gather bytes), fp32 accum.
//
// Gather is issue/occupancy-bound (R4: issue=46%, occ=50.5%, regs=44).
// This round: 16 lanes per row with uint4(half8) loads -> one LDG.128 serves
// TWO edges per warp instruction (lo half-warp edge a, hi half-warp edge b);
// paired int2/float2 col/val loads; launch_bounds(256,6) for 75% occ ceiling.
// Half-warp partial accumulators combined once per segment via shfl_down(16).
//
// (R5 was an infra failure — container died before running; identical resubmit.)

#define MAX_SEG (1 << 20)
#define NODES_CAP 131072

__device__ int   g_seg[MAX_SEG + 1];
__device__ uint4 g_xh[NODES_CAP * 16];   // fp16 X: 16 x uint4 (8 halves) per row

__device__ __forceinline__ unsigned h2_as_u32(__half2 h) {
    union { __half2 h; unsigned u; } c; c.h = h; return c.u;
}
__device__ __forceinline__ __half2 u32_as_h2(unsigned u) {
    union { unsigned u; __half2 h; } c; c.u = u; return c.h;
}

__global__ __launch_bounds__(256) void prep_kernel(
    const float4* __restrict__ X,      // [nodes*32] float4
    const int*    __restrict__ rows,   // [nnz] sorted
    int nnz, int num_segments,
    int n_groups,                      // nodes*16
    int convert_blocks)
{
    if ((int)blockIdx.x < convert_blocks) {
        const int g = blockIdx.x * 256 + threadIdx.x;
        if (g >= n_groups) return;
        const float4 f0 = __ldg(&X[g * 2 + 0]);
        const float4 f1 = __ldg(&X[g * 2 + 1]);
        uint4 h;
        h.x = h2_as_u32(__floats2half2_rn(f0.x, f0.y));
        h.y = h2_as_u32(__floats2half2_rn(f0.z, f0.w));
        h.z = h2_as_u32(__floats2half2_rn(f1.x, f1.y));
        h.w = h2_as_u32(__floats2half2_rn(f1.z, f1.w));
        g_xh[g] = h;
    } else {
        const int e = (blockIdx.x - convert_blocks) * 256 + threadIdx.x;
        if (e >= nnz) return;
        const int r  = __ldg(&rows[e]);
        const int rp = (e == 0) ? -1 : __ldg(&rows[e - 1]);
        for (int s = rp + 1; s <= r; ++s) g_seg[s] = e;
        if (e == nnz - 1)
            for (int s = r + 1; s <= num_segments; ++s) g_seg[s] = nnz;
    }
}

__global__ __launch_bounds__(256, 6) void gather_kernel(
    const float* __restrict__ vals,
    const int*   __restrict__ cols,
    float4*      __restrict__ out,    // [num_segments, 32] float4
    int num_segments)
{
    const int warp = (blockIdx.x * blockDim.x + threadIdx.x) >> 5;
    const int lane = threadIdx.x & 31;
    if (warp >= num_segments) return;

    const int start = g_seg[warp];
    const int end   = g_seg[warp + 1];

    const int  g  = lane & 15;         // dim-group: dims [8g, 8g+8)
    const bool hi = lane >= 16;        // hi half-warp handles the odd edge

    float a0=0.f,a1=0.f,a2=0.f,a3=0.f,a4=0.f,a5=0.f,a6=0.f,a7=0.f;

    #define ACCUM(H, V)                                                      \
    {                                                                        \
        const float2 p0 = __half22float2(u32_as_h2((H).x));                  \
        const float2 p1 = __half22float2(u32_as_h2((H).y));                  \
        const float2 p2 = __half22float2(u32_as_h2((H).z));                  \
        const float2 p3 = __half22float2(u32_as_h2((H).w));                  \
        a0 += (V)*p0.x; a1 += (V)*p0.y; a2 += (V)*p1.x; a3 += (V)*p1.y;      \
        a4 += (V)*p2.x; a5 += (V)*p2.y; a6 += (V)*p3.x; a7 += (V)*p3.y;      \
    }

    int e = start;

    // head: make e even so int2/float2 loads are aligned
    if ((e & 1) && e < end) {
        const int   c = __ldg(cols + e);
        const float v = hi ? 0.f : __ldg(vals + e);
        const uint4 h = g_xh[(unsigned)c * 16u + g];
        ACCUM(h, v);
        ++e;
    }

    const int2*   cols2 = reinterpret_cast<const int2*>(cols);
    const float2* vals2 = reinterpret_cast<const float2*>(vals);

    // main: 8 edges (4 pairs) per iteration; each LDG.128 serves 2 edges
    #pragma unroll 1
    for (; e + 8 <= end; e += 8) {
        const int   p  = e >> 1;
        const int2   cA = __ldg(cols2 + p + 0);
        const int2   cB = __ldg(cols2 + p + 1);
        const int2   cC = __ldg(cols2 + p + 2);
        const int2   cD = __ldg(cols2 + p + 3);
        const float2 vA = __ldg(vals2 + p + 0);
        const float2 vB = __ldg(vals2 + p + 1);
        const float2 vC = __ldg(vals2 + p + 2);
        const float2 vD = __ldg(vals2 + p + 3);

        const int c0 = hi ? cA.y : cA.x;  const float v0 = hi ? vA.y : vA.x;
        const int c1 = hi ? cB.y : cB.x;  const float v1 = hi ? vB.y : vB.x;
        const int c2 = hi ? cC.y : cC.x;  const float v2 = hi ? vC.y : vC.x;
        const int c3 = hi ? cD.y : cD.x;  const float v3 = hi ? vD.y : vD.x;

        // 4 LDG.128 in flight, covering 8 edges
        const uint4 h0 = g_xh[(unsigned)c0 * 16u + g];
        const uint4 h1 = g_xh[(unsigned)c1 * 16u + g];
        const uint4 h2 = g_xh[(unsigned)c2 * 16u + g];
        const uint4 h3 = g_xh[(unsigned)c3 * 16u + g];

        ACCUM(h0, v0); ACCUM(h1, v1); ACCUM(h2, v2); ACCUM(h3, v3);
    }

    // tail: single edges, lo half-warp only contributes
    for (; e < end; ++e) {
        const int   c = __ldg(cols + e);
        const float v = hi ? 0.f : __ldg(vals + e);
        const uint4 h = g_xh[(unsigned)c * 16u + g];
        ACCUM(h, v);
    }
    #undef ACCUM

    // combine hi half-warp partials into lo half-warp
    a0 += __shfl_down_sync(0xffffffffu, a0, 16);
    a1 += __shfl_down_sync(0xffffffffu, a1, 16);
    a2 += __shfl_down_sync(0xffffffffu, a2, 16);
    a3 += __shfl_down_sync(0xffffffffu, a3, 16);
    a4 += __shfl_down_sync(0xffffffffu, a4, 16);
    a5 += __shfl_down_sync(0xffffffffu, a5, 16);
    a6 += __shfl_down_sync(0xffffffffu, a6, 16);
    a7 += __shfl_down_sync(0xffffffffu, a7, 16);

    if (!hi) {
        float4* o = out + (unsigned)warp * 32u + (unsigned)g * 2u;
        o[0] = make_float4(a0, a1, a2, a3);
        o[1] = make_float4(a4, a5, a6, a7);
    }
}

extern "C" void kernel_launch(void* const* d_in, const int* in_sizes, int n_in,
                              void* d_out, int out_size)
{
    const float4* X    = (const float4*)d_in[0];
    const float*  vals = (const float*) d_in[1];
    const int*    rows = (const int*)   d_in[2];
    const int*    cols = (const int*)   d_in[3];
    float4*       out  = (float4*)      d_out;

    const int nnz   = in_sizes[1];
    int nodes       = in_sizes[0] / 128;
    if (nodes > NODES_CAP) nodes = NODES_CAP;
    int num_segments = out_size / 128;
    if (num_segments > MAX_SEG) num_segments = MAX_SEG;

    const int n_groups       = nodes * 16;
    const int convert_blocks = (n_groups + 255) / 256;
    const int offset_blocks  = (nnz + 255) / 256;

    prep_kernel<<<convert_blocks + offset_blocks, 256>>>(
        X, rows, nnz, num_segments, n_groups, convert_blocks);

    const int threads = 256;
    const int blocks  = (num_segments * 32 + threads - 1) / threads;
    gather_kernel<<<blocks, threads>>>(vals, cols, out, num_segments);
}

// round 7
// speedup vs baseline: 1.7057x; 1.0666x over previous
#include <cuda_runtime.h>
#include <cuda_fp16.h>

// SubgraphProjection: out[s,:] = sum_{e: rows[e]==s} vals[e] * X[cols[e],:]
// rows sorted, DIM=128. fp16 scratch for X, fp32 accumulation.
//
// R6 showed gather is issue-COUNT bound (issue=59%, L2=39%) and each LDG.128
// already moves 2 full fp16 rows (byte-optimal). This round cuts non-load
// issues: (1) 8B edge records {col, half2(v,v)} loaded per-lane (kills 8 SELs
// + 4 idx loads per 8-edge iter, no alignment peel), (2) HFMA2 fp16 partial
// accumulation (<=4 terms per lane), flushed to fp32 each iteration
// (16 HFMA2 + 8 CVT + 8 FADD replaces 16 CVT + 32 FFMA).

#define MAX_SEG   (1 << 20)
#define NODES_CAP 131072
#define NNZ_CAP   (1 << 21)

__device__ int   g_seg[MAX_SEG + 1];
__device__ uint4 g_xh[NODES_CAP * 16];   // fp16 X: 16 x uint4 (8 halves) per row
__device__ int2  g_rec[NNZ_CAP];         // per edge: {col, half2(v,v) bits}

__device__ __forceinline__ unsigned h2_as_u32(__half2 h) {
    union { __half2 h; unsigned u; } c; c.h = h; return c.u;
}
__device__ __forceinline__ __half2 u32_as_h2(unsigned u) {
    union { unsigned u; __half2 h; } c; c.u = u; return c.h;
}

__global__ __launch_bounds__(256) void prep_kernel(
    const float4* __restrict__ X,      // [nodes*32] float4
    const int*    __restrict__ rows,   // [nnz] sorted
    const int*    __restrict__ cols,   // [nnz]
    const float*  __restrict__ vals,   // [nnz]
    int nnz, int num_segments,
    int n_groups,                      // nodes*16
    int convert_blocks)
{
    if ((int)blockIdx.x < convert_blocks) {
        const int g = blockIdx.x * 256 + threadIdx.x;
        if (g >= n_groups) return;
        const float4 f0 = __ldg(&X[g * 2 + 0]);
        const float4 f1 = __ldg(&X[g * 2 + 1]);
        uint4 h;
        h.x = h2_as_u32(__floats2half2_rn(f0.x, f0.y));
        h.y = h2_as_u32(__floats2half2_rn(f0.z, f0.w));
        h.z = h2_as_u32(__floats2half2_rn(f1.x, f1.y));
        h.w = h2_as_u32(__floats2half2_rn(f1.z, f1.w));
        g_xh[g] = h;
    } else {
        const int e = (blockIdx.x - convert_blocks) * 256 + threadIdx.x;
        if (e >= nnz) return;
        // CSR offsets from sorted rows (boundary detection)
        const int r  = __ldg(&rows[e]);
        const int rp = (e == 0) ? -1 : __ldg(&rows[e - 1]);
        for (int s = rp + 1; s <= r; ++s) g_seg[s] = e;
        if (e == nnz - 1)
            for (int s = r + 1; s <= num_segments; ++s) g_seg[s] = nnz;
        // edge record: col + splatted half2 value
        const float v = __ldg(&vals[e]);
        g_rec[e] = make_int2(__ldg(&cols[e]),
                             (int)h2_as_u32(__floats2half2_rn(v, v)));
    }
}

__global__ __launch_bounds__(256, 6) void gather_kernel(
    float4* __restrict__ out,          // [num_segments, 32] float4
    int num_segments)
{
    const int warp = (blockIdx.x * blockDim.x + threadIdx.x) >> 5;
    const int lane = threadIdx.x & 31;
    if (warp >= num_segments) return;

    const int start = g_seg[warp];
    const int end   = g_seg[warp + 1];

    const int g  = lane & 15;          // dim-group: dims [8g, 8g+8)
    const int hi = lane >> 4;          // 0: even edges, 1: odd edges

    const int2* __restrict__ recs = g_rec;

    float a0=0.f,a1=0.f,a2=0.f,a3=0.f,a4=0.f,a5=0.f,a6=0.f,a7=0.f;
    const __half2 hz = u32_as_h2(0u);
    __half2 s0 = hz, s1 = hz, s2 = hz, s3 = hz;

    #define HACC(H, VH)                                     \
    {                                                       \
        s0 = __hfma2(u32_as_h2((H).x), (VH), s0);           \
        s1 = __hfma2(u32_as_h2((H).y), (VH), s1);           \
        s2 = __hfma2(u32_as_h2((H).z), (VH), s2);           \
        s3 = __hfma2(u32_as_h2((H).w), (VH), s3);           \
    }
    #define FLUSH()                                         \
    {                                                       \
        float2 f;                                           \
        f = __half22float2(s0); a0 += f.x; a1 += f.y;       \
        f = __half22float2(s1); a2 += f.x; a3 += f.y;       \
        f = __half22float2(s2); a4 += f.x; a5 += f.y;       \
        f = __half22float2(s3); a6 += f.x; a7 += f.y;       \
        s0 = hz; s1 = hz; s2 = hz; s3 = hz;                 \
    }

    int e = start;
    #pragma unroll 1
    for (; e + 8 <= end; e += 8) {
        // each lane loads its own edge's record (no SEL, no alignment req)
        const int2 rA = __ldg(recs + e + 0 + hi);
        const int2 rB = __ldg(recs + e + 2 + hi);
        const int2 rC = __ldg(recs + e + 4 + hi);
        const int2 rD = __ldg(recs + e + 6 + hi);

        // 4 LDG.128 in flight; each serves 2 edges across the warp
        const uint4 h0 = g_xh[(unsigned)rA.x * 16u + g];
        const uint4 h1 = g_xh[(unsigned)rB.x * 16u + g];
        const uint4 h2 = g_xh[(unsigned)rC.x * 16u + g];
        const uint4 h3 = g_xh[(unsigned)rD.x * 16u + g];

        HACC(h0, u32_as_h2((unsigned)rA.y));
        HACC(h1, u32_as_h2((unsigned)rB.y));
        HACC(h2, u32_as_h2((unsigned)rC.y));
        HACC(h3, u32_as_h2((unsigned)rD.y));
        FLUSH();   // <=4 fp16 terms per lane per flush
    }

    // tail: <8 edges, 2 at a time (hi lane masked on an odd final edge)
    for (; e < end; e += 2) {
        const int  idx   = e + hi;
        const bool valid = idx < end;
        const int2 r = __ldg(recs + (valid ? idx : e));
        const __half2 vh = valid ? u32_as_h2((unsigned)r.y) : hz;
        const uint4 h = g_xh[(unsigned)r.x * 16u + g];
        HACC(h, vh);
    }
    FLUSH();
    #undef HACC
    #undef FLUSH

    // combine hi half-warp partials into lo half-warp
    a0 += __shfl_down_sync(0xffffffffu, a0, 16);
    a1 += __shfl_down_sync(0xffffffffu, a1, 16);
    a2 += __shfl_down_sync(0xffffffffu, a2, 16);
    a3 += __shfl_down_sync(0xffffffffu, a3, 16);
    a4 += __shfl_down_sync(0xffffffffu, a4, 16);
    a5 += __shfl_down_sync(0xffffffffu, a5, 16);
    a6 += __shfl_down_sync(0xffffffffu, a6, 16);
    a7 += __shfl_down_sync(0xffffffffu, a7, 16);

    if (!hi) {
        float4* o = out + (unsigned)warp * 32u + (unsigned)g * 2u;
        o[0] = make_float4(a0, a1, a2, a3);
        o[1] = make_float4(a4, a5, a6, a7);
    }
}

extern "C" void kernel_launch(void* const* d_in, const int* in_sizes, int n_in,
                              void* d_out, int out_size)
{
    const float4* X    = (const float4*)d_in[0];
    const float*  vals = (const float*) d_in[1];
    const int*    rows = (const int*)   d_in[2];
    const int*    cols = (const int*)   d_in[3];
    float4*       out  = (float4*)      d_out;

    int nnz = in_sizes[1];
    if (nnz > NNZ_CAP) nnz = NNZ_CAP;
    int nodes = in_sizes[0] / 128;
    if (nodes > NODES_CAP) nodes = NODES_CAP;
    int num_segments = out_size / 128;
    if (num_segments > MAX_SEG) num_segments = MAX_SEG;

    const int n_groups       = nodes * 16;
    const int convert_blocks = (n_groups + 255) / 256;
    const int offset_blocks  = (nnz + 255) / 256;

    prep_kernel<<<convert_blocks + offset_blocks, 256>>>(
        X, rows, cols, vals, nnz, num_segments, n_groups, convert_blocks);

    const int threads = 256;
    const int blocks  = (num_segments * 32 + threads - 1) / threads;
    gather_kernel<<<blocks, threads>>>(out, num_segments);
}

// round 9
// speedup vs baseline: 1.7778x; 1.0422x over previous
#include <cuda_runtime.h>
#include <cuda_fp16.h>

// SubgraphProjection: out[s,:] = sum_{e: rows[e]==s} vals[e] * X[cols[e],:]
// rows sorted, DIM=128. fp16 scratch X, fp32 accumulation.
//
// R7 analysis: prep is DRAM-byte-bound (~109MB), gather is at 93% of the L2
// transfer cap (~448MB). R8 cuts bytes + issues:
//  1) drop g_rec: prep writes only g_hv (6.4MB splat-half2), never reads cols
//     (prep 108.8 -> 96.2 MB). Gather loads cols/g_hv per-lane (broadcast-pair
//     addresses, L1-line-hot).
//  2) flush fp16 partials to fp32 every 16 edges instead of 8 (halves the
//     8CVT+8FADD flush cost; <=8 fp16 terms per partial, rel_err ~5e-4).
//  3) persistent warp-per-segment loop (grid = SMs*6 blocks) to remove the
//     7-wave tail quantization.
// (R8 bench was an infra failure — container died before running; identical
//  resubmit.)

#define MAX_SEG   (1 << 20)
#define NODES_CAP 131072
#define NNZ_CAP   (1 << 21)
#define NUM_SMS   148
#define BLOCKS_PER_SM 6

__device__ int      g_seg[MAX_SEG + 1];
__device__ uint4    g_xh[NODES_CAP * 16];  // fp16 X: 16 x uint4 (8 halves) per row
__device__ unsigned g_hv[NNZ_CAP];         // per edge: half2(v,v) bits

__device__ __forceinline__ unsigned h2_as_u32(__half2 h) {
    union { __half2 h; unsigned u; } c; c.h = h; return c.u;
}
__device__ __forceinline__ __half2 u32_as_h2(unsigned u) {
    union { unsigned u; __half2 h; } c; c.u = u; return c.h;
}

__global__ __launch_bounds__(256) void prep_kernel(
    const float4* __restrict__ X,      // [nodes*32] float4
    const int*    __restrict__ rows,   // [nnz] sorted
    const float*  __restrict__ vals,   // [nnz]
    int nnz, int num_segments,
    int n_groups,                      // nodes*16
    int convert_blocks)
{
    if ((int)blockIdx.x < convert_blocks) {
        const int g = blockIdx.x * 256 + threadIdx.x;
        if (g >= n_groups) return;
        const float4 f0 = __ldg(&X[g * 2 + 0]);
        const float4 f1 = __ldg(&X[g * 2 + 1]);
        uint4 h;
        h.x = h2_as_u32(__floats2half2_rn(f0.x, f0.y));
        h.y = h2_as_u32(__floats2half2_rn(f0.z, f0.w));
        h.z = h2_as_u32(__floats2half2_rn(f1.x, f1.y));
        h.w = h2_as_u32(__floats2half2_rn(f1.z, f1.w));
        g_xh[g] = h;
    } else {
        const int e = (blockIdx.x - convert_blocks) * 256 + threadIdx.x;
        if (e >= nnz) return;
        // CSR offsets from sorted rows (boundary detection)
        const int r  = __ldg(&rows[e]);
        const int rp = (e == 0) ? -1 : __ldg(&rows[e - 1]);
        for (int s = rp + 1; s <= r; ++s) g_seg[s] = e;
        if (e == nnz - 1)
            for (int s = r + 1; s <= num_segments; ++s) g_seg[s] = nnz;
        // splatted half2 value
        const float v = __ldg(&vals[e]);
        g_hv[e] = h2_as_u32(__floats2half2_rn(v, v));
    }
}

__global__ __launch_bounds__(256, BLOCKS_PER_SM) void gather_kernel(
    const int* __restrict__ cols,      // [nnz]
    float4*    __restrict__ out,       // [num_segments, 32] float4
    int num_segments, int total_warps)
{
    const int warp0 = (blockIdx.x * blockDim.x + threadIdx.x) >> 5;
    const int lane  = threadIdx.x & 31;
    const int g  = lane & 15;          // dim-group: dims [8g, 8g+8)
    const int hi = lane >> 4;          // 0: even edges, 1: odd edges
    const __half2 hz = u32_as_h2(0u);

    for (int seg = warp0; seg < num_segments; seg += total_warps) {
        const int start = g_seg[seg];
        const int end   = g_seg[seg + 1];

        float a0=0.f,a1=0.f,a2=0.f,a3=0.f,a4=0.f,a5=0.f,a6=0.f,a7=0.f;
        __half2 s0 = hz, s1 = hz, s2 = hz, s3 = hz;

        #define HACC(H, VH)                                 \
        {                                                   \
            s0 = __hfma2(u32_as_h2((H).x), (VH), s0);       \
            s1 = __hfma2(u32_as_h2((H).y), (VH), s1);       \
            s2 = __hfma2(u32_as_h2((H).z), (VH), s2);       \
            s3 = __hfma2(u32_as_h2((H).w), (VH), s3);       \
        }
        #define BODY8(E)                                                     \
        {                                                                    \
            const int i0 = (E) + hi, i1 = (E) + 2 + hi,                      \
                      i2 = (E) + 4 + hi, i3 = (E) + 6 + hi;                  \
            const int c0 = __ldg(cols + i0), c1 = __ldg(cols + i1);          \
            const int c2 = __ldg(cols + i2), c3 = __ldg(cols + i3);          \
            const unsigned u0 = __ldg(g_hv + i0), u1 = __ldg(g_hv + i1);     \
            const unsigned u2 = __ldg(g_hv + i2), u3 = __ldg(g_hv + i3);     \
            const uint4 h0 = g_xh[(unsigned)c0 * 16u + g];                   \
            const uint4 h1 = g_xh[(unsigned)c1 * 16u + g];                   \
            const uint4 h2 = g_xh[(unsigned)c2 * 16u + g];                   \
            const uint4 h3 = g_xh[(unsigned)c3 * 16u + g];                   \
            HACC(h0, u32_as_h2(u0)); HACC(h1, u32_as_h2(u1));                \
            HACC(h2, u32_as_h2(u2)); HACC(h3, u32_as_h2(u3));                \
        }
        #define FLUSH()                                     \
        {                                                   \
            float2 f;                                       \
            f = __half22float2(s0); a0 += f.x; a1 += f.y;   \
            f = __half22float2(s1); a2 += f.x; a3 += f.y;   \
            f = __half22float2(s2); a4 += f.x; a5 += f.y;   \
            f = __half22float2(s3); a6 += f.x; a7 += f.y;   \
            s0 = hz; s1 = hz; s2 = hz; s3 = hz;             \
        }

        int e = start;
        #pragma unroll 1
        for (; e + 16 <= end; e += 16) {   // <=8 fp16 terms per partial
            BODY8(e); BODY8(e + 8);
            FLUSH();
        }
        if (e + 8 <= end) { BODY8(e); e += 8; }
        // tail: 2 edges at a time (hi lane masked on an odd final edge)
        for (; e < end; e += 2) {
            const int  idx   = e + hi;
            const bool valid = idx < end;
            const int  c = __ldg(cols + (valid ? idx : e));
            const __half2 vh = valid ? u32_as_h2(__ldg(g_hv + idx)) : hz;
            const uint4 h = g_xh[(unsigned)c * 16u + g];
            HACC(h, vh);
        }
        FLUSH();
        #undef HACC
        #undef BODY8
        #undef FLUSH

        // combine hi half-warp partials into lo half-warp
        a0 += __shfl_down_sync(0xffffffffu, a0, 16);
        a1 += __shfl_down_sync(0xffffffffu, a1, 16);
        a2 += __shfl_down_sync(0xffffffffu, a2, 16);
        a3 += __shfl_down_sync(0xffffffffu, a3, 16);
        a4 += __shfl_down_sync(0xffffffffu, a4, 16);
        a5 += __shfl_down_sync(0xffffffffu, a5, 16);
        a6 += __shfl_down_sync(0xffffffffu, a6, 16);
        a7 += __shfl_down_sync(0xffffffffu, a7, 16);

        if (!hi) {
            float4* o = out + (unsigned)seg * 32u + (unsigned)g * 2u;
            o[0] = make_float4(a0, a1, a2, a3);
            o[1] = make_float4(a4, a5, a6, a7);
        }
    }
}

extern "C" void kernel_launch(void* const* d_in, const int* in_sizes, int n_in,
                              void* d_out, int out_size)
{
    const float4* X    = (const float4*)d_in[0];
    const float*  vals = (const float*) d_in[1];
    const int*    rows = (const int*)   d_in[2];
    const int*    cols = (const int*)   d_in[3];
    float4*       out  = (float4*)      d_out;

    int nnz = in_sizes[1];
    if (nnz > NNZ_CAP) nnz = NNZ_CAP;
    int nodes = in_sizes[0] / 128;
    if (nodes > NODES_CAP) nodes = NODES_CAP;
    int num_segments = out_size / 128;
    if (num_segments > MAX_SEG) num_segments = MAX_SEG;

    const int n_groups       = nodes * 16;
    const int convert_blocks = (n_groups + 255) / 256;
    const int offset_blocks  = (nnz + 255) / 256;

    prep_kernel<<<convert_blocks + offset_blocks, 256>>>(
        X, rows, vals, nnz, num_segments, n_groups, convert_blocks);

    const int blocks      = NUM_SMS * BLOCKS_PER_SM;   // persistent, 1 wave
    const int total_warps = blocks * (256 / 32);
    gather_kernel<<<blocks, 256>>>(cols, out, num_segments, total_warps);
}

// round 12
// speedup vs baseline: 1.9164x; 1.0780x over previous
#include <cuda_runtime.h>
#include <cuda_fp16.h>

// SubgraphProjection: out[s,:] = sum_{e: rows[e]==s} vals[e] * X[cols[e],:]
// rows sorted, DIM=128. fp16 scratch X, fp32 accumulation.
//
// R9: gather is AT the ~6300 B/cyc LTS cap; its byte floor is reached. Slack
// is in prep (~19.6us vs ~13us floor). This round (minimal diff vs known-good
// R9): drop the g_hv scratch entirely — gather loads vals fp32 per-lane and
// splats with __float2half2_rn (byte-neutral for gather; saves prep a 6.4MB
// read + 6.4MB write). Offsets pass is the R9-proven two-load version (the
// rows[e-1] reread is same-line L1-hot, byte-free).
// Gather: 16 lanes/row uint4 loads (1 LDG.128 = 2 edges), HFMA2 partials
// (<=8 fp16 terms) flushed to fp32 every 16 edges, persistent grid.

#define MAX_SEG   (1 << 20)
#define NODES_CAP 131072
#define NNZ_CAP   (1 << 21)
#define NUM_SMS   148
#define BLOCKS_PER_SM 6

__device__ int   g_seg[MAX_SEG + 1];
__device__ uint4 g_xh[NODES_CAP * 16];   // fp16 X: 16 x uint4 (8 halves) per row

__device__ __forceinline__ unsigned h2_as_u32(__half2 h) {
    union { __half2 h; unsigned u; } c; c.h = h; return c.u;
}
__device__ __forceinline__ __half2 u32_as_h2(unsigned u) {
    union { unsigned u; __half2 h; } c; c.u = u; return c.h;
}

__global__ __launch_bounds__(256) void prep_kernel(
    const float4* __restrict__ X,      // [nodes*32] float4
    const int*    __restrict__ rows,   // [nnz] sorted
    int nnz, int num_segments,
    int n_groups,                      // nodes*16
    int convert_blocks)
{
    if ((int)blockIdx.x < convert_blocks) {
        const int g = blockIdx.x * 256 + threadIdx.x;
        if (g >= n_groups) return;
        const float4 f0 = __ldg(&X[g * 2 + 0]);
        const float4 f1 = __ldg(&X[g * 2 + 1]);
        uint4 h;
        h.x = h2_as_u32(__floats2half2_rn(f0.x, f0.y));
        h.y = h2_as_u32(__floats2half2_rn(f0.z, f0.w));
        h.z = h2_as_u32(__floats2half2_rn(f1.x, f1.y));
        h.w = h2_as_u32(__floats2half2_rn(f1.z, f1.w));
        g_xh[g] = h;
    } else {
        const int e = (blockIdx.x - convert_blocks) * 256 + threadIdx.x;
        if (e >= nnz) return;
        // CSR offsets from sorted rows (boundary detection)
        const int r  = __ldg(&rows[e]);
        const int rp = (e == 0) ? -1 : __ldg(&rows[e - 1]);
        for (int s = rp + 1; s <= r; ++s) g_seg[s] = e;
        if (e == nnz - 1)
            for (int s = r + 1; s <= num_segments; ++s) g_seg[s] = nnz;
    }
}

__global__ __launch_bounds__(256, BLOCKS_PER_SM) void gather_kernel(
    const int*   __restrict__ cols,    // [nnz]
    const float* __restrict__ vals,    // [nnz]
    float4*      __restrict__ out,     // [num_segments, 32] float4
    int num_segments, int total_warps)
{
    const int warp0 = (blockIdx.x * blockDim.x + threadIdx.x) >> 5;
    const int lane  = threadIdx.x & 31;
    const int g  = lane & 15;          // dim-group: dims [8g, 8g+8)
    const int hi = lane >> 4;          // 0: even edges, 1: odd edges
    const __half2 hz = u32_as_h2(0u);

    for (int seg = warp0; seg < num_segments; seg += total_warps) {
        const int start = g_seg[seg];
        const int end   = g_seg[seg + 1];

        float a0=0.f,a1=0.f,a2=0.f,a3=0.f,a4=0.f,a5=0.f,a6=0.f,a7=0.f;
        __half2 s0 = hz, s1 = hz, s2 = hz, s3 = hz;

        #define HACC(H, VH)                                 \
        {                                                   \
            s0 = __hfma2(u32_as_h2((H).x), (VH), s0);       \
            s1 = __hfma2(u32_as_h2((H).y), (VH), s1);       \
            s2 = __hfma2(u32_as_h2((H).z), (VH), s2);       \
            s3 = __hfma2(u32_as_h2((H).w), (VH), s3);       \
        }
        #define BODY8(E)                                                     \
        {                                                                    \
            const int i0 = (E) + hi, i1 = (E) + 2 + hi,                      \
                      i2 = (E) + 4 + hi, i3 = (E) + 6 + hi;                  \
            const int c0 = __ldg(cols + i0), c1 = __ldg(cols + i1);          \
            const int c2 = __ldg(cols + i2), c3 = __ldg(cols + i3);          \
            const float w0 = __ldg(vals + i0), w1 = __ldg(vals + i1);        \
            const float w2 = __ldg(vals + i2), w3 = __ldg(vals + i3);        \
            const uint4 h0 = g_xh[(unsigned)c0 * 16u + g];                   \
            const uint4 h1 = g_xh[(unsigned)c1 * 16u + g];                   \
            const uint4 h2 = g_xh[(unsigned)c2 * 16u + g];                   \
            const uint4 h3 = g_xh[(unsigned)c3 * 16u + g];                   \
            HACC(h0, __float2half2_rn(w0)); HACC(h1, __float2half2_rn(w1));  \
            HACC(h2, __float2half2_rn(w2)); HACC(h3, __float2half2_rn(w3));  \
        }
        #define FLUSH()                                     \
        {                                                   \
            float2 f;                                       \
            f = __half22float2(s0); a0 += f.x; a1 += f.y;   \
            f = __half22float2(s1); a2 += f.x; a3 += f.y;   \
            f = __half22float2(s2); a4 += f.x; a5 += f.y;   \
            f = __half22float2(s3); a6 += f.x; a7 += f.y;   \
            s0 = hz; s1 = hz; s2 = hz; s3 = hz;             \
        }

        int e = start;
        #pragma unroll 1
        for (; e + 16 <= end; e += 16) {   // <=8 fp16 terms per partial
            BODY8(e); BODY8(e + 8);
            FLUSH();
        }
        if (e + 8 <= end) { BODY8(e); e += 8; }
        // tail: 2 edges at a time (hi lane masked on an odd final edge)
        for (; e < end; e += 2) {
            const int  idx   = e + hi;
            const bool valid = idx < end;
            const int  c = __ldg(cols + (valid ? idx : e));
            const __half2 vh = valid ? __float2half2_rn(__ldg(vals + idx)) : hz;
            const uint4 h = g_xh[(unsigned)c * 16u + g];
            HACC(h, vh);
        }
        FLUSH();
        #undef HACC
        #undef BODY8
        #undef FLUSH

        // combine hi half-warp partials into lo half-warp
        a0 += __shfl_down_sync(0xffffffffu, a0, 16);
        a1 += __shfl_down_sync(0xffffffffu, a1, 16);
        a2 += __shfl_down_sync(0xffffffffu, a2, 16);
        a3 += __shfl_down_sync(0xffffffffu, a3, 16);
        a4 += __shfl_down_sync(0xffffffffu, a4, 16);
        a5 += __shfl_down_sync(0xffffffffu, a5, 16);
        a6 += __shfl_down_sync(0xffffffffu, a6, 16);
        a7 += __shfl_down_sync(0xffffffffu, a7, 16);

        if (!hi) {
            float4* o = out + (unsigned)seg * 32u + (unsigned)g * 2u;
            o[0] = make_float4(a0, a1, a2, a3);
            o[1] = make_float4(a4, a5, a6, a7);
        }
    }
}

extern "C" void kernel_launch(void* const* d_in, const int* in_sizes, int n_in,
                              void* d_out, int out_size)
{
    const float4* X    = (const float4*)d_in[0];
    const float*  vals = (const float*) d_in[1];
    const int*    rows = (const int*)   d_in[2];
    const int*    cols = (const int*)   d_in[3];
    float4*       out  = (float4*)      d_out;

    int nnz = in_sizes[1];
    if (nnz > NNZ_CAP) nnz = NNZ_CAP;
    int nodes = in_sizes[0] / 128;
    if (nodes > NODES_CAP) nodes = NODES_CAP;
    int num_segments = out_size / 128;
    if (num_segments > MAX_SEG) num_segments = MAX_SEG;

    const int n_groups       = nodes * 16;
    const int convert_blocks = (n_groups + 255) / 256;
    const int offset_blocks  = (nnz + 255) / 256;

    prep_kernel<<<convert_blocks + offset_blocks, 256>>>(
        X, rows, nnz, num_segments, n_groups, convert_blocks);

    const int blocks      = NUM_SMS * BLOCKS_PER_SM;   // persistent, 1 wave
    const int total_warps = blocks * (256 / 32);
    gather_kernel<<<blocks, 256>>>(cols, vals, out, num_segments, total_warps);
}